// round 4
// baseline (speedup 1.0000x reference)
#include <cuda_runtime.h>
#include <cuda_fp16.h>
#include <cstdint>

#define BATCH 16
#define RDIM 256
#define CDIM 256
#define NPIX (RDIM*CDIM)
#define F 64
#define M_TOTAL (BATCH*NPIX)   /* 1048576 rows */

// ---------------- scratch ----------------------------------------------------
__device__ __half g_Htp[(size_t)M_TOTAL * F];   // pre-BN linear output, fp16, 128MB
__device__ float g_sum[F];
__device__ float g_sumsq[F];
__device__ float g_scale[F];
__device__ float g_bias[F];

// ---------------- helpers ----------------------------------------------------
__device__ __forceinline__ uint32_t f2tf(float x) {
    uint32_t u;
    asm("cvt.rna.tf32.f32 %0, %1;" : "=r"(u) : "f"(x));
    return u;
}

__device__ __forceinline__ void cp_async16(void* smem_dst, const void* gsrc) {
    uint32_t s = (uint32_t)__cvta_generic_to_shared(smem_dst);
    asm volatile("cp.async.cg.shared.global [%0], [%1], 16;\n" :: "r"(s), "l"(gsrc));
}

__device__ __forceinline__ float dval(int i, int j) {
    int ri = 3 - (i == 0) - (i == RDIM - 1);
    int rj = 3 - (j == 0) - (j == CDIM - 1);
    return rsqrtf((float)(ri * rj) + 1e-5f);
}

// ---------------- K0: zero stats ---------------------------------------------
__global__ void k_zero() {
    int t = threadIdx.x;
    if (t < F) { g_sum[t] = 0.f; g_sumsq[t] = 0.f; }
}

// ---------------- K1: Ht = H @ W (tf32 mma), cp.async double buffer ----------
// CTA: 256 threads (8 warps). Tile 128 rows; each warp owns 16 rows.
// 8 tiles of 128 rows = 1024 rows per CTA.
#define SHS 68
#define TILES_PER_CTA 8
#define ROWS_PER_CTA (TILES_PER_CTA * 128)

__global__ __launch_bounds__(256)
void k_gemm(const float* __restrict__ H, const float* __restrict__ W) {
    extern __shared__ float smem[];
    float* sW   = smem;                        // 64*SHS
    float* sHa  = smem + 64 * SHS;             // 128*SHS (buffer A)
    float* sHb  = sHa + 128 * SHS;             // 128*SHS (buffer B)
    float* sSum = sHb + 128 * SHS;             // 64
    float* sSq  = sSum + F;                    // 64

    const int tid  = threadIdx.x;
    const int warp = tid >> 5;
    const int lane = tid & 31;
    const int g    = lane >> 2;
    const int tg   = lane & 3;
    const int mrow = warp * 16;                // 8 warps x 16 rows = 128

    if (tid < F) { sSum[tid] = 0.f; sSq[tid] = 0.f; }

    // Load W (64x64) -> tf32 (rna) in smem, once per CTA
    for (int idx = tid; idx < 64 * 16; idx += 256) {
        int r = idx >> 4, c4 = (idx & 15) * 4;
        float4 v = ((const float4*)W)[idx];
        float4 o;
        o.x = __uint_as_float(f2tf(v.x));
        o.y = __uint_as_float(f2tf(v.y));
        o.z = __uint_as_float(f2tf(v.z));
        o.w = __uint_as_float(f2tf(v.w));
        *(float4*)&sW[r * SHS + c4] = o;
    }

    const float* ctaH = H + (size_t)blockIdx.x * ROWS_PER_CTA * F;

    auto issue_tile = [&](int t, float* buf) {
        const float* src = ctaH + (size_t)t * 128 * F;
#pragma unroll
        for (int k = 0; k < 8; k++) {
            int idx = tid + 256 * k;
            int r = idx >> 4, c4 = (idx & 15) * 4;
            cp_async16(&buf[r * SHS + c4], src + (size_t)idx * 4);
        }
        asm volatile("cp.async.commit_group;\n" ::);
    };

    issue_tile(0, sHa);

    // Cross-tile stat accumulators (registers)
    float s[8][2], q[8][2];
#pragma unroll
    for (int nt = 0; nt < 8; nt++) { s[nt][0] = s[nt][1] = q[nt][0] = q[nt][1] = 0.f; }

#pragma unroll 1
    for (int t = 0; t < TILES_PER_CTA; t++) {
        float* cur = (t & 1) ? sHb : sHa;
        float* nxt = (t & 1) ? sHa : sHb;
        if (t < TILES_PER_CTA - 1) {
            issue_tile(t + 1, nxt);
            asm volatile("cp.async.wait_group 1;\n" ::);
        } else {
            asm volatile("cp.async.wait_group 0;\n" ::);
        }
        __syncthreads();

        float acc[8][4];
#pragma unroll
        for (int nt = 0; nt < 8; nt++)
#pragma unroll
            for (int i = 0; i < 4; i++) acc[nt][i] = 0.f;

#pragma unroll
        for (int kk = 0; kk < 8; kk++) {
            const int k0 = kk * 8;
            uint32_t a0c = __float_as_uint(cur[(mrow + g    ) * SHS + k0 + tg    ]);
            uint32_t a1c = __float_as_uint(cur[(mrow + g + 8) * SHS + k0 + tg    ]);
            uint32_t a2c = __float_as_uint(cur[(mrow + g    ) * SHS + k0 + tg + 4]);
            uint32_t a3c = __float_as_uint(cur[(mrow + g + 8) * SHS + k0 + tg + 4]);
#pragma unroll
            for (int nt = 0; nt < 8; nt++) {
                uint32_t b0 = __float_as_uint(sW[(k0 + tg    ) * SHS + nt * 8 + g]);
                uint32_t b1 = __float_as_uint(sW[(k0 + tg + 4) * SHS + nt * 8 + g]);
                asm volatile(
                    "mma.sync.aligned.m16n8k8.row.col.f32.tf32.tf32.f32 "
                    "{%0,%1,%2,%3}, {%4,%5,%6,%7}, {%8,%9}, {%0,%1,%2,%3};"
                    : "+f"(acc[nt][0]), "+f"(acc[nt][1]),
                      "+f"(acc[nt][2]), "+f"(acc[nt][3])
                    : "r"(a0c), "r"(a1c), "r"(a2c), "r"(a3c),
                      "r"(b0), "r"(b1));
            }
        }

        // Epilogue: fp16 store + stat accumulation in registers
        __half* outp = g_Htp + ((size_t)blockIdx.x * ROWS_PER_CTA + (size_t)t * 128) * F;
#pragma unroll
        for (int nt = 0; nt < 8; nt++) {
            int colb = nt * 8 + 2 * tg;
            float a0 = acc[nt][0], a1 = acc[nt][1];
            float a2 = acc[nt][2], a3 = acc[nt][3];
            *(__half2*)&outp[(size_t)(mrow + g    ) * F + colb] = __floats2half2_rn(a0, a1);
            *(__half2*)&outp[(size_t)(mrow + g + 8) * F + colb] = __floats2half2_rn(a2, a3);
            s[nt][0] += a0 + a2;           s[nt][1] += a1 + a3;
            q[nt][0] += a0 * a0 + a2 * a2; q[nt][1] += a1 * a1 + a3 * a3;
        }
        __syncthreads();   // all warps done reading `cur` before it is refilled
    }

    // Reduce stats: butterfly over g, then smem atomics, then 64 global atomics
#pragma unroll
    for (int off = 4; off < 32; off <<= 1) {
#pragma unroll
        for (int nt = 0; nt < 8; nt++) {
            s[nt][0] += __shfl_xor_sync(0xffffffffu, s[nt][0], off);
            s[nt][1] += __shfl_xor_sync(0xffffffffu, s[nt][1], off);
            q[nt][0] += __shfl_xor_sync(0xffffffffu, q[nt][0], off);
            q[nt][1] += __shfl_xor_sync(0xffffffffu, q[nt][1], off);
        }
    }
    if (lane < 4) {
#pragma unroll
        for (int nt = 0; nt < 8; nt++) {
            int c = nt * 8 + 2 * lane;
            atomicAdd(&sSum[c],     s[nt][0]);
            atomicAdd(&sSum[c + 1], s[nt][1]);
            atomicAdd(&sSq[c],      q[nt][0]);
            atomicAdd(&sSq[c + 1],  q[nt][1]);
        }
    }
    __syncthreads();
    if (tid < F) {
        atomicAdd(&g_sum[tid],   sSum[tid]);
        atomicAdd(&g_sumsq[tid], sSq[tid]);
    }
}

// ---------------- K2: finalize BN scale/bias ---------------------------------
__global__ void k_stats(const float* __restrict__ gamma, const float* __restrict__ beta) {
    int o = threadIdx.x;
    if (o < F) {
        float inv_m = 1.f / (float)M_TOTAL;
        float mean = g_sum[o] * inv_m;
        float var  = g_sumsq[o] * inv_m - mean * mean;
        float is   = rsqrtf(var + 1e-5f);
        float sc   = gamma[o] * is;
        g_scale[o] = sc;
        g_bias[o]  = beta[o] - mean * sc;
    }
}

// ---------------- K3: BN + ReLU + normalized 3x3 stencil (fp16 in) -----------
// CTA: 288 threads = 18 cols (16 out + 2 halo) x 16 half4 chunks.
// 2 output rows per __syncthreads (4 smem buffers), loads prefetched 2 ahead.
__global__ __launch_bounds__(288, 5)
void k_stencil(float* __restrict__ out) {
    __shared__ float4 cs[4][18][16];

    const int tid   = threadIdx.x;
    const int chunk = tid & 15;      // 0..15 (4 channels each)
    const int colL  = tid >> 4;      // 0..17
    const int b     = blockIdx.z;
    const int j0    = blockIdx.x * 16;
    const int i0    = blockIdx.y * 32;
    const int j     = j0 - 1 + colL;
    const bool jin  = (j >= 0 && j < CDIM);
    const bool isOut = (colL >= 1 && colL <= 16);

    const float4 sc = *(const float4*)&g_scale[chunk * 4];
    const float4 bs = *(const float4*)&g_bias[chunk * 4];
    const __half* base = g_Htp + (size_t)b * NPIX * F;

    auto rawload = [&](int i) -> uint2 {
        if (!jin || i < 0 || i >= RDIM) return make_uint2(0u, 0u);
        return *(const uint2*)&base[((size_t)i * CDIM + j) * F + chunk * 4];
    };
    auto bnrow = [&](uint2 rw, int i) -> float4 {
        if (!jin || i < 0 || i >= RDIM) return make_float4(0.f, 0.f, 0.f, 0.f);
        float2 f0 = __half22float2(*(__half2*)&rw.x);
        float2 f1 = __half22float2(*(__half2*)&rw.y);
        float d = dval(i, j);
        float4 r;
        r.x = fmaxf(fmaf(f0.x, sc.x, bs.x), 0.f) * d;
        r.y = fmaxf(fmaf(f0.y, sc.y, bs.y), 0.f) * d;
        r.z = fmaxf(fmaf(f1.x, sc.z, bs.z), 0.f) * d;
        r.w = fmaxf(fmaf(f1.y, sc.w, bs.w), 0.f) * d;
        return r;
    };

    float4 p = bnrow(rawload(i0 - 1), i0 - 1);
    float4 c = bnrow(rawload(i0), i0);
    uint2 rn  = rawload(i0 + 1);
    uint2 rn2 = rawload(i0 + 2);
    int bb = 0;

    for (int r = 0; r < 16; r++) {
        const int i = i0 + 2 * r;
        uint2 rn3 = rawload(i + 3);
        uint2 rn4 = rawload(i + 4);
        float4 n  = bnrow(rn,  i + 1);
        float4 n2 = bnrow(rn2, i + 2);
        float4 v0, v1;
        v0.x = p.x + c.x + n.x;   v1.x = c.x + n.x + n2.x;
        v0.y = p.y + c.y + n.y;   v1.y = c.y + n.y + n2.y;
        v0.z = p.z + c.z + n.z;   v1.z = c.z + n.z + n2.z;
        v0.w = p.w + c.w + n.w;   v1.w = c.w + n.w + n2.w;
        cs[bb][colL][chunk]     = v0;
        cs[bb + 1][colL][chunk] = v1;
        __syncthreads();
        if (isOut) {
            float4 l0 = cs[bb][colL - 1][chunk];
            float4 r0 = cs[bb][colL + 1][chunk];
            float dc0 = dval(i, j);
            float4 o0;
            o0.x = (l0.x + v0.x + r0.x) * dc0;
            o0.y = (l0.y + v0.y + r0.y) * dc0;
            o0.z = (l0.z + v0.z + r0.z) * dc0;
            o0.w = (l0.w + v0.w + r0.w) * dc0;
            *(float4*)&out[((size_t)b * NPIX + (size_t)i * CDIM + j) * F + chunk * 4] = o0;

            float4 l1 = cs[bb + 1][colL - 1][chunk];
            float4 r1 = cs[bb + 1][colL + 1][chunk];
            float dc1 = dval(i + 1, j);
            float4 o1;
            o1.x = (l1.x + v1.x + r1.x) * dc1;
            o1.y = (l1.y + v1.y + r1.y) * dc1;
            o1.z = (l1.z + v1.z + r1.z) * dc1;
            o1.w = (l1.w + v1.w + r1.w) * dc1;
            *(float4*)&out[((size_t)b * NPIX + (size_t)(i + 1) * CDIM + j) * F + chunk * 4] = o1;
        }
        p = n; c = n2; rn = rn3; rn2 = rn4; bb ^= 2;
    }
}

// ---------------- launch ------------------------------------------------------
extern "C" void kernel_launch(void* const* d_in, const int* in_sizes, int n_in,
                              void* d_out, int out_size) {
    (void)in_sizes; (void)n_in; (void)out_size;
    const float* H     = (const float*)d_in[0];
    const float* W     = (const float*)d_in[1];
    const float* gamma = (const float*)d_in[2];
    const float* beta  = (const float*)d_in[3];
    float* out = (float*)d_out;

    const int smemK1 = (64 * SHS + 2 * 128 * SHS + 2 * F) * sizeof(float);  // ~87.5KB
    cudaFuncSetAttribute(k_gemm, cudaFuncAttributeMaxDynamicSharedMemorySize, smemK1);

    k_zero<<<1, 64>>>();
    k_gemm<<<M_TOTAL / ROWS_PER_CTA, 256, smemK1>>>(H, W);
    k_stats<<<1, 64>>>(gamma, beta);
    dim3 g3(CDIM / 16, RDIM / 32, BATCH);
    k_stencil<<<g3, 288>>>(out);
}

// round 6
// speedup vs baseline: 1.1763x; 1.1763x over previous
#include <cuda_runtime.h>
#include <cuda_fp16.h>
#include <cstdint>

#define BATCH 16
#define RDIM 256
#define CDIM 256
#define NPIX (RDIM*CDIM)
#define F 64
#define M_TOTAL (BATCH*NPIX)   /* 1048576 rows */

// ---------------- scratch ----------------------------------------------------
__device__ __half g_Htp[(size_t)M_TOTAL * F];   // pre-BN linear output, fp16, 128MB
__device__ float g_sum[F];
__device__ float g_sumsq[F];
__device__ float g_scale[F];
__device__ float g_bias[F];

// ---------------- helpers ----------------------------------------------------
__device__ __forceinline__ uint32_t h2_bits(__half2 h) {
    uint32_t u;
    __builtin_memcpy(&u, &h, 4);
    return u;
}

__device__ __forceinline__ float dval(int i, int j) {
    int ri = 3 - (i == 0) - (i == RDIM - 1);
    int rj = 3 - (j == 0) - (j == CDIM - 1);
    return rsqrtf((float)(ri * rj) + 1e-5f);
}

// ---------------- K0: zero stats ---------------------------------------------
__global__ void k_zero() {
    int t = threadIdx.x;
    if (t < F) { g_sum[t] = 0.f; g_sumsq[t] = 0.f; }
}

// ---------------- K1: Ht = H @ W, fp16 mma, A direct from global -------------
// CTA: 128 threads (4 warps). Each warp streams TPW tiles of 16 rows.
// W transposed fp16 in smem (stride 72 halves -> conflict-free b-frag loads).
#define TPW 16                      /* tiles (of 16 rows) per warp */
#define WSTRIDE 72

__global__ __launch_bounds__(128)
void k_gemm(const float* __restrict__ H, const float* __restrict__ W) {
    __shared__ __half sWt[64 * WSTRIDE];   // Wt[n][k]
    __shared__ float sSum[F], sSq[F];

    const int tid  = threadIdx.x;
    const int warp = tid >> 5;
    const int lane = tid & 31;
    const int g    = lane >> 2;    // 0..7
    const int tg   = lane & 3;     // 0..3

    if (tid < F) { sSum[tid] = 0.f; sSq[tid] = 0.f; }

    // Build Wt (fp16, transposed) in smem
    for (int idx = tid; idx < 64 * 64; idx += 128) {
        int k = idx >> 6, n = idx & 63;
        sWt[n * WSTRIDE + k] = __float2half(W[idx]);
    }
    __syncthreads();

    // Stat accumulators: cols (nt*8 + 2tg) and (+1)
    float s[8][2], q[8][2];
#pragma unroll
    for (int nt = 0; nt < 8; nt++) { s[nt][0] = s[nt][1] = q[nt][0] = q[nt][1] = 0.f; }

    const size_t warpRow0 = ((size_t)blockIdx.x * 4 + warp) * (TPW * 16);

#pragma unroll 1
    for (int t = 0; t < TPW; t++) {
        const size_t rb = warpRow0 + (size_t)t * 16;
        const float* Ar = H + rb * F;

        // Load A fragments for all 4 k-steps (16 x LDG.64, front-batched)
        float2 af[4][4];
#pragma unroll
        for (int ks = 0; ks < 4; ks++) {
            int kc = ks * 16 + 2 * tg;
            af[ks][0] = *(const float2*)&Ar[(size_t)(g    ) * F + kc    ];
            af[ks][1] = *(const float2*)&Ar[(size_t)(g + 8) * F + kc    ];
            af[ks][2] = *(const float2*)&Ar[(size_t)(g    ) * F + kc + 8];
            af[ks][3] = *(const float2*)&Ar[(size_t)(g + 8) * F + kc + 8];
        }

        float acc[8][4];
#pragma unroll
        for (int nt = 0; nt < 8; nt++)
#pragma unroll
            for (int i = 0; i < 4; i++) acc[nt][i] = 0.f;

#pragma unroll
        for (int ks = 0; ks < 4; ks++) {
            uint32_t a0 = h2_bits(__floats2half2_rn(af[ks][0].x, af[ks][0].y));
            uint32_t a1 = h2_bits(__floats2half2_rn(af[ks][1].x, af[ks][1].y));
            uint32_t a2 = h2_bits(__floats2half2_rn(af[ks][2].x, af[ks][2].y));
            uint32_t a3 = h2_bits(__floats2half2_rn(af[ks][3].x, af[ks][3].y));
            int kc = ks * 16 + 2 * tg;
#pragma unroll
            for (int nt = 0; nt < 8; nt++) {
                uint32_t b0 = *(const uint32_t*)&sWt[(nt * 8 + g) * WSTRIDE + kc    ];
                uint32_t b1 = *(const uint32_t*)&sWt[(nt * 8 + g) * WSTRIDE + kc + 8];
                asm volatile(
                    "mma.sync.aligned.m16n8k16.row.col.f32.f16.f16.f32 "
                    "{%0,%1,%2,%3}, {%4,%5,%6,%7}, {%8,%9}, {%0,%1,%2,%3};"
                    : "+f"(acc[nt][0]), "+f"(acc[nt][1]),
                      "+f"(acc[nt][2]), "+f"(acc[nt][3])
                    : "r"(a0), "r"(a1), "r"(a2), "r"(a3),
                      "r"(b0), "r"(b1));
            }
        }

        // Epilogue: fp16 store + stat accumulation
        __half* outp = g_Htp + rb * F;
#pragma unroll
        for (int nt = 0; nt < 8; nt++) {
            int colb = nt * 8 + 2 * tg;
            float c0 = acc[nt][0], c1 = acc[nt][1];
            float c2 = acc[nt][2], c3 = acc[nt][3];
            *(__half2*)&outp[(size_t)(g    ) * F + colb] = __floats2half2_rn(c0, c1);
            *(__half2*)&outp[(size_t)(g + 8) * F + colb] = __floats2half2_rn(c2, c3);
            s[nt][0] += c0 + c2;           s[nt][1] += c1 + c3;
            q[nt][0] += c0 * c0 + c2 * c2; q[nt][1] += c1 * c1 + c3 * c3;
        }
    }

    // Reduce stats: butterfly over g, smem atomics, 64 global atomics
#pragma unroll
    for (int off = 4; off < 32; off <<= 1) {
#pragma unroll
        for (int nt = 0; nt < 8; nt++) {
            s[nt][0] += __shfl_xor_sync(0xffffffffu, s[nt][0], off);
            s[nt][1] += __shfl_xor_sync(0xffffffffu, s[nt][1], off);
            q[nt][0] += __shfl_xor_sync(0xffffffffu, q[nt][0], off);
            q[nt][1] += __shfl_xor_sync(0xffffffffu, q[nt][1], off);
        }
    }
    if (lane < 4) {
#pragma unroll
        for (int nt = 0; nt < 8; nt++) {
            int c = nt * 8 + 2 * lane;
            atomicAdd(&sSum[c],     s[nt][0]);
            atomicAdd(&sSum[c + 1], s[nt][1]);
            atomicAdd(&sSq[c],      q[nt][0]);
            atomicAdd(&sSq[c + 1],  q[nt][1]);
        }
    }
    __syncthreads();
    if (tid < F) {
        atomicAdd(&g_sum[tid],   sSum[tid]);
        atomicAdd(&g_sumsq[tid], sSq[tid]);
    }
}

// ---------------- K2: finalize BN scale/bias ---------------------------------
__global__ void k_stats(const float* __restrict__ gamma, const float* __restrict__ beta) {
    int o = threadIdx.x;
    if (o < F) {
        float inv_m = 1.f / (float)M_TOTAL;
        float mean = g_sum[o] * inv_m;
        float var  = g_sumsq[o] * inv_m - mean * mean;
        float is   = rsqrtf(var + 1e-5f);
        float sc   = gamma[o] * is;
        g_scale[o] = sc;
        g_bias[o]  = beta[o] - mean * sc;
    }
}

// ---------------- K3: BN + ReLU + normalized 3x3 stencil (fp16 in) -----------
// CTA: 288 threads = 18 cols (16 out + 2 halo) x 16 half4 chunks.
// 2 output rows per __syncthreads (4 smem buffers), loads prefetched 2 ahead.
__global__ __launch_bounds__(288, 4)
void k_stencil(float* __restrict__ out) {
    __shared__ float4 cs[4][18][16];

    const int tid   = threadIdx.x;
    const int chunk = tid & 15;      // 0..15 (4 channels each)
    const int colL  = tid >> 4;      // 0..17
    const int b     = blockIdx.z;
    const int j0    = blockIdx.x * 16;
    const int i0    = blockIdx.y * 32;
    const int j     = j0 - 1 + colL;
    const bool jin  = (j >= 0 && j < CDIM);
    const bool isOut = (colL >= 1 && colL <= 16);

    const float4 sc = *(const float4*)&g_scale[chunk * 4];
    const float4 bs = *(const float4*)&g_bias[chunk * 4];
    const __half* base = g_Htp + (size_t)b * NPIX * F;

    auto rawload = [&](int i) -> uint2 {
        if (!jin || i < 0 || i >= RDIM) return make_uint2(0u, 0u);
        return *(const uint2*)&base[((size_t)i * CDIM + j) * F + chunk * 4];
    };
    auto bnrow = [&](uint2 rw, int i) -> float4 {
        if (!jin || i < 0 || i >= RDIM) return make_float4(0.f, 0.f, 0.f, 0.f);
        float2 f0 = __half22float2(*(__half2*)&rw.x);
        float2 f1 = __half22float2(*(__half2*)&rw.y);
        float d = dval(i, j);
        float4 r;
        r.x = fmaxf(fmaf(f0.x, sc.x, bs.x), 0.f) * d;
        r.y = fmaxf(fmaf(f0.y, sc.y, bs.y), 0.f) * d;
        r.z = fmaxf(fmaf(f1.x, sc.z, bs.z), 0.f) * d;
        r.w = fmaxf(fmaf(f1.y, sc.w, bs.w), 0.f) * d;
        return r;
    };

    float4 p = bnrow(rawload(i0 - 1), i0 - 1);
    float4 c = bnrow(rawload(i0), i0);
    uint2 rn  = rawload(i0 + 1);
    uint2 rn2 = rawload(i0 + 2);
    int bb = 0;

    for (int r = 0; r < 16; r++) {
        const int i = i0 + 2 * r;
        uint2 rn3 = rawload(i + 3);
        uint2 rn4 = rawload(i + 4);
        float4 n  = bnrow(rn,  i + 1);
        float4 n2 = bnrow(rn2, i + 2);
        float4 v0, v1;
        v0.x = p.x + c.x + n.x;   v1.x = c.x + n.x + n2.x;
        v0.y = p.y + c.y + n.y;   v1.y = c.y + n.y + n2.y;
        v0.z = p.z + c.z + n.z;   v1.z = c.z + n.z + n2.z;
        v0.w = p.w + c.w + n.w;   v1.w = c.w + n.w + n2.w;
        cs[bb][colL][chunk]     = v0;
        cs[bb + 1][colL][chunk] = v1;
        __syncthreads();
        if (isOut) {
            float4 l0 = cs[bb][colL - 1][chunk];
            float4 r0 = cs[bb][colL + 1][chunk];
            float dc0 = dval(i, j);
            float4 o0;
            o0.x = (l0.x + v0.x + r0.x) * dc0;
            o0.y = (l0.y + v0.y + r0.y) * dc0;
            o0.z = (l0.z + v0.z + r0.z) * dc0;
            o0.w = (l0.w + v0.w + r0.w) * dc0;
            *(float4*)&out[((size_t)b * NPIX + (size_t)i * CDIM + j) * F + chunk * 4] = o0;

            float4 l1 = cs[bb + 1][colL - 1][chunk];
            float4 r1 = cs[bb + 1][colL + 1][chunk];
            float dc1 = dval(i + 1, j);
            float4 o1;
            o1.x = (l1.x + v1.x + r1.x) * dc1;
            o1.y = (l1.y + v1.y + r1.y) * dc1;
            o1.z = (l1.z + v1.z + r1.z) * dc1;
            o1.w = (l1.w + v1.w + r1.w) * dc1;
            *(float4*)&out[((size_t)b * NPIX + (size_t)(i + 1) * CDIM + j) * F + chunk * 4] = o1;
        }
        p = n; c = n2; rn = rn3; rn2 = rn4; bb ^= 2;
    }
}

// ---------------- launch ------------------------------------------------------
extern "C" void kernel_launch(void* const* d_in, const int* in_sizes, int n_in,
                              void* d_out, int out_size) {
    (void)in_sizes; (void)n_in; (void)out_size;
    const float* H     = (const float*)d_in[0];
    const float* W     = (const float*)d_in[1];
    const float* gamma = (const float*)d_in[2];
    const float* beta  = (const float*)d_in[3];
    float* out = (float*)d_out;

    k_zero<<<1, 64>>>();
    const int rows_per_cta = 4 * TPW * 16;   // 1024
    k_gemm<<<M_TOTAL / rows_per_cta, 128>>>(H, W);
    k_stats<<<1, 64>>>(gamma, beta);
    dim3 g3(CDIM / 16, RDIM / 32, BATCH);
    k_stencil<<<g3, 288>>>(out);
}

// round 7
// speedup vs baseline: 1.2382x; 1.0527x over previous
#include <cuda_runtime.h>
#include <cuda_fp16.h>
#include <cstdint>

#define BATCH 16
#define RDIM 256
#define CDIM 256
#define NPIX (RDIM*CDIM)
#define F 64
#define M_TOTAL (BATCH*NPIX)   /* 1048576 rows */

// ---------------- scratch ----------------------------------------------------
__device__ __half g_Htp[(size_t)M_TOTAL * F];   // pre-BN linear output, fp16, 128MB
__device__ float g_sum[F];
__device__ float g_sumsq[F];
__device__ float g_scale[F];
__device__ float g_bias[F];

// ---------------- helpers ----------------------------------------------------
__device__ __forceinline__ uint32_t h2_bits(__half2 h) {
    uint32_t u;
    __builtin_memcpy(&u, &h, 4);
    return u;
}

__device__ __forceinline__ float dval(int i, int j) {
    int ri = 3 - (i == 0) - (i == RDIM - 1);
    int rj = 3 - (j == 0) - (j == CDIM - 1);
    return rsqrtf((float)(ri * rj) + 1e-5f);
}

// ---------------- K0: zero stats ---------------------------------------------
__global__ void k_zero() {
    int t = threadIdx.x;
    if (t < F) { g_sum[t] = 0.f; g_sumsq[t] = 0.f; }
}

// ---------------- K1: Ht = H @ W, fp16 mma, smem-staged dense I/O ------------
// CTA: 128 threads (4 warps). Each warp streams TPW tiles of 16 rows through a
// private fp16 smem buffer: dense LDG.128 in, fragments via LDS, epilogue via
// STS + dense STG.128. Only warp-local syncs.
#define TPW 16                      /* tiles (of 16 rows) per warp */
#define WSTRIDE 72                  /* halves; fragment banks = 4g+tg (no conflict) */

__global__ __launch_bounds__(128)
void k_gemm(const float* __restrict__ H, const float* __restrict__ W) {
    __shared__ __half sWt[64 * WSTRIDE];        // Wt[n][k], 18KB
    __shared__ __half sA[4][16 * WSTRIDE];      // per-warp staging, 2.25KB each
    __shared__ float sSum[F], sSq[F];

    const int tid  = threadIdx.x;
    const int warp = tid >> 5;
    const int lane = tid & 31;
    const int g    = lane >> 2;    // 0..7
    const int tg   = lane & 3;     // 0..3

    if (tid < F) { sSum[tid] = 0.f; sSq[tid] = 0.f; }

    // Build Wt (fp16, transposed) in smem
    for (int idx = tid; idx < 64 * 64; idx += 128) {
        int k = idx >> 6, n = idx & 63;
        sWt[n * WSTRIDE + k] = __float2half(W[idx]);
    }
    __syncthreads();

    __half* myA = sA[warp];

    // Stat accumulators: cols (nt*8 + 2tg) and (+1)
    float s[8][2], q[8][2];
#pragma unroll
    for (int nt = 0; nt < 8; nt++) { s[nt][0] = s[nt][1] = q[nt][0] = q[nt][1] = 0.f; }

    const size_t warpRow0 = ((size_t)blockIdx.x * 4 + warp) * (TPW * 16);

#pragma unroll 1
    for (int t = 0; t < TPW; t++) {
        const size_t rb = warpRow0 + (size_t)t * 16;
        const float4* Ar = (const float4*)(H + rb * F);

        // Dense load: 8 x LDG.128 per lane-set (16 rows x 64 floats)
        float4 v[8];
#pragma unroll
        for (int r = 0; r < 8; r++) v[r] = Ar[lane + 32 * r];

        // Convert to fp16 and stage in smem
#pragma unroll
        for (int r = 0; r < 8; r++) {
            int f   = lane + 32 * r;
            int row = f >> 4, c4 = f & 15;
            uint2 pk;
            pk.x = h2_bits(__floats2half2_rn(v[r].x, v[r].y));
            pk.y = h2_bits(__floats2half2_rn(v[r].z, v[r].w));
            *(uint2*)&myA[row * WSTRIDE + c4 * 4] = pk;
        }
        __syncwarp();

        float acc[8][4];
#pragma unroll
        for (int nt = 0; nt < 8; nt++)
#pragma unroll
            for (int i = 0; i < 4; i++) acc[nt][i] = 0.f;

#pragma unroll
        for (int ks = 0; ks < 4; ks++) {
            const int kc = ks * 16 + 2 * tg;
            uint32_t a0 = *(const uint32_t*)&myA[(g    ) * WSTRIDE + kc    ];
            uint32_t a1 = *(const uint32_t*)&myA[(g + 8) * WSTRIDE + kc    ];
            uint32_t a2 = *(const uint32_t*)&myA[(g    ) * WSTRIDE + kc + 8];
            uint32_t a3 = *(const uint32_t*)&myA[(g + 8) * WSTRIDE + kc + 8];
#pragma unroll
            for (int nt = 0; nt < 8; nt++) {
                uint32_t b0 = *(const uint32_t*)&sWt[(nt * 8 + g) * WSTRIDE + kc    ];
                uint32_t b1 = *(const uint32_t*)&sWt[(nt * 8 + g) * WSTRIDE + kc + 8];
                asm volatile(
                    "mma.sync.aligned.m16n8k16.row.col.f32.f16.f16.f32 "
                    "{%0,%1,%2,%3}, {%4,%5,%6,%7}, {%8,%9}, {%0,%1,%2,%3};"
                    : "+f"(acc[nt][0]), "+f"(acc[nt][1]),
                      "+f"(acc[nt][2]), "+f"(acc[nt][3])
                    : "r"(a0), "r"(a1), "r"(a2), "r"(a3),
                      "r"(b0), "r"(b1));
            }
        }
        __syncwarp();   // all fragment reads done before buffer reuse

        // Epilogue: stats + fp16 fragments -> smem (conflict-free: banks 4g+4nt+tg)
#pragma unroll
        for (int nt = 0; nt < 8; nt++) {
            int colb = nt * 8 + 2 * tg;
            float c0 = acc[nt][0], c1 = acc[nt][1];
            float c2 = acc[nt][2], c3 = acc[nt][3];
            *(__half2*)&myA[(g    ) * WSTRIDE + colb] = __floats2half2_rn(c0, c1);
            *(__half2*)&myA[(g + 8) * WSTRIDE + colb] = __floats2half2_rn(c2, c3);
            s[nt][0] += c0 + c2;           s[nt][1] += c1 + c3;
            q[nt][0] += c0 * c0 + c2 * c2; q[nt][1] += c1 * c1 + c3 * c3;
        }
        __syncwarp();

        // Dense store: 4 x (LDS.128 + STG.128) covering 16 rows x 128B
        __half* outp = g_Htp + rb * F;
#pragma unroll
        for (int r = 0; r < 4; r++) {
            int u   = lane + 32 * r;        // 16B unit index, 128 total
            int row = u >> 3, cu = u & 7;
            uint4 x = *(const uint4*)&myA[row * WSTRIDE + cu * 8];
            *(uint4*)&outp[(size_t)row * F + cu * 8] = x;
        }
        __syncwarp();   // dense reads done before next tile's staging STS
    }

    // Reduce stats: butterfly over g, smem atomics, 64 global atomics
#pragma unroll
    for (int off = 4; off < 32; off <<= 1) {
#pragma unroll
        for (int nt = 0; nt < 8; nt++) {
            s[nt][0] += __shfl_xor_sync(0xffffffffu, s[nt][0], off);
            s[nt][1] += __shfl_xor_sync(0xffffffffu, s[nt][1], off);
            q[nt][0] += __shfl_xor_sync(0xffffffffu, q[nt][0], off);
            q[nt][1] += __shfl_xor_sync(0xffffffffu, q[nt][1], off);
        }
    }
    if (lane < 4) {
#pragma unroll
        for (int nt = 0; nt < 8; nt++) {
            int c = nt * 8 + 2 * lane;
            atomicAdd(&sSum[c],     s[nt][0]);
            atomicAdd(&sSum[c + 1], s[nt][1]);
            atomicAdd(&sSq[c],      q[nt][0]);
            atomicAdd(&sSq[c + 1],  q[nt][1]);
        }
    }
    __syncthreads();
    if (tid < F) {
        atomicAdd(&g_sum[tid],   sSum[tid]);
        atomicAdd(&g_sumsq[tid], sSq[tid]);
    }
}

// ---------------- K2: finalize BN scale/bias ---------------------------------
__global__ void k_stats(const float* __restrict__ gamma, const float* __restrict__ beta) {
    int o = threadIdx.x;
    if (o < F) {
        float inv_m = 1.f / (float)M_TOTAL;
        float mean = g_sum[o] * inv_m;
        float var  = g_sumsq[o] * inv_m - mean * mean;
        float is   = rsqrtf(var + 1e-5f);
        float sc   = gamma[o] * is;
        g_scale[o] = sc;
        g_bias[o]  = beta[o] - mean * sc;
    }
}

// ---------------- K3: BN + ReLU + normalized 3x3 stencil (fp16 in) -----------
// CTA: 288 threads = 18 cols (16 out + 2 halo) x 16 half4 chunks.
// 2 output rows per __syncthreads (4 smem buffers), loads prefetched 2 ahead.
__global__ __launch_bounds__(288, 4)
void k_stencil(float* __restrict__ out) {
    __shared__ float4 cs[4][18][16];

    const int tid   = threadIdx.x;
    const int chunk = tid & 15;      // 0..15 (4 channels each)
    const int colL  = tid >> 4;      // 0..17
    const int b     = blockIdx.z;
    const int j0    = blockIdx.x * 16;
    const int i0    = blockIdx.y * 32;
    const int j     = j0 - 1 + colL;
    const bool jin  = (j >= 0 && j < CDIM);
    const bool isOut = (colL >= 1 && colL <= 16);

    const float4 sc = *(const float4*)&g_scale[chunk * 4];
    const float4 bs = *(const float4*)&g_bias[chunk * 4];
    const __half* base = g_Htp + (size_t)b * NPIX * F;

    auto rawload = [&](int i) -> uint2 {
        if (!jin || i < 0 || i >= RDIM) return make_uint2(0u, 0u);
        return *(const uint2*)&base[((size_t)i * CDIM + j) * F + chunk * 4];
    };
    auto bnrow = [&](uint2 rw, int i) -> float4 {
        if (!jin || i < 0 || i >= RDIM) return make_float4(0.f, 0.f, 0.f, 0.f);
        float2 f0 = __half22float2(*(__half2*)&rw.x);
        float2 f1 = __half22float2(*(__half2*)&rw.y);
        float d = dval(i, j);
        float4 r;
        r.x = fmaxf(fmaf(f0.x, sc.x, bs.x), 0.f) * d;
        r.y = fmaxf(fmaf(f0.y, sc.y, bs.y), 0.f) * d;
        r.z = fmaxf(fmaf(f1.x, sc.z, bs.z), 0.f) * d;
        r.w = fmaxf(fmaf(f1.y, sc.w, bs.w), 0.f) * d;
        return r;
    };

    float4 p = bnrow(rawload(i0 - 1), i0 - 1);
    float4 c = bnrow(rawload(i0), i0);
    uint2 rn  = rawload(i0 + 1);
    uint2 rn2 = rawload(i0 + 2);
    int bb = 0;

    for (int r = 0; r < 16; r++) {
        const int i = i0 + 2 * r;
        uint2 rn3 = rawload(i + 3);
        uint2 rn4 = rawload(i + 4);
        float4 n  = bnrow(rn,  i + 1);
        float4 n2 = bnrow(rn2, i + 2);
        float4 v0, v1;
        v0.x = p.x + c.x + n.x;   v1.x = c.x + n.x + n2.x;
        v0.y = p.y + c.y + n.y;   v1.y = c.y + n.y + n2.y;
        v0.z = p.z + c.z + n.z;   v1.z = c.z + n.z + n2.z;
        v0.w = p.w + c.w + n.w;   v1.w = c.w + n.w + n2.w;
        cs[bb][colL][chunk]     = v0;
        cs[bb + 1][colL][chunk] = v1;
        __syncthreads();
        if (isOut) {
            float4 l0 = cs[bb][colL - 1][chunk];
            float4 r0 = cs[bb][colL + 1][chunk];
            float dc0 = dval(i, j);
            float4 o0;
            o0.x = (l0.x + v0.x + r0.x) * dc0;
            o0.y = (l0.y + v0.y + r0.y) * dc0;
            o0.z = (l0.z + v0.z + r0.z) * dc0;
            o0.w = (l0.w + v0.w + r0.w) * dc0;
            *(float4*)&out[((size_t)b * NPIX + (size_t)i * CDIM + j) * F + chunk * 4] = o0;

            float4 l1 = cs[bb + 1][colL - 1][chunk];
            float4 r1 = cs[bb + 1][colL + 1][chunk];
            float dc1 = dval(i + 1, j);
            float4 o1;
            o1.x = (l1.x + v1.x + r1.x) * dc1;
            o1.y = (l1.y + v1.y + r1.y) * dc1;
            o1.z = (l1.z + v1.z + r1.z) * dc1;
            o1.w = (l1.w + v1.w + r1.w) * dc1;
            *(float4*)&out[((size_t)b * NPIX + (size_t)(i + 1) * CDIM + j) * F + chunk * 4] = o1;
        }
        p = n; c = n2; rn = rn3; rn2 = rn4; bb ^= 2;
    }
}

// ---------------- launch ------------------------------------------------------
extern "C" void kernel_launch(void* const* d_in, const int* in_sizes, int n_in,
                              void* d_out, int out_size) {
    (void)in_sizes; (void)n_in; (void)out_size;
    const float* H     = (const float*)d_in[0];
    const float* W     = (const float*)d_in[1];
    const float* gamma = (const float*)d_in[2];
    const float* beta  = (const float*)d_in[3];
    float* out = (float*)d_out;

    k_zero<<<1, 64>>>();
    const int rows_per_cta = 4 * TPW * 16;   // 1024
    k_gemm<<<M_TOTAL / rows_per_cta, 128>>>(H, W);
    k_stats<<<1, 64>>>(gamma, beta);
    dim3 g3(CDIM / 16, RDIM / 32, BATCH);
    k_stencil<<<g3, 288>>>(out);
}

// round 8
// speedup vs baseline: 1.3867x; 1.1199x over previous
#include <cuda_runtime.h>
#include <cuda_fp16.h>
#include <cstdint>

#define BATCH 16
#define RDIM 256
#define CDIM 256
#define NPIX (RDIM*CDIM)
#define F 64
#define M_TOTAL (BATCH*NPIX)   /* 1048576 rows */

// ---------------- scratch ----------------------------------------------------
__device__ __half g_Htp[(size_t)M_TOTAL * F];   // pre-BN linear output, fp16, 128MB
__device__ float g_sum[F];
__device__ float g_sumsq[F];
__device__ float g_scale[F];
__device__ float g_bias[F];

// ---------------- helpers ----------------------------------------------------
__device__ __forceinline__ uint32_t h2_bits(__half2 h) {
    uint32_t u;
    __builtin_memcpy(&u, &h, 4);
    return u;
}

__device__ __forceinline__ void cp_async16(void* smem_dst, const void* gsrc) {
    uint32_t s = (uint32_t)__cvta_generic_to_shared(smem_dst);
    asm volatile("cp.async.cg.shared.global [%0], [%1], 16;\n" :: "r"(s), "l"(gsrc));
}

__device__ __forceinline__ float dval(int i, int j) {
    int ri = 3 - (i == 0) - (i == RDIM - 1);
    int rj = 3 - (j == 0) - (j == CDIM - 1);
    return rsqrtf((float)(ri * rj) + 1e-5f);
}

// ---------------- K0: zero stats ---------------------------------------------
__global__ void k_zero() {
    int t = threadIdx.x;
    if (t < F) { g_sum[t] = 0.f; g_sumsq[t] = 0.f; }
}

// ---------------- K1: Ht = H @ W, fp16 mma, cp.async per-warp pipeline -------
// CTA: 128 threads (4 warps). Each warp streams TPW tiles of 16 rows through a
// double-buffered fp32 staging area filled by cp.async (tile t+1 in flight
// while tile t computes). Consumed buffer is recycled as fp16 epilogue staging.
#define TPW 16                      /* tiles (of 16 rows) per warp */
#define FSTRIDE 72                  /* floats: conflict-free frag LDS.64 phases */
#define WSTRIDE 72                  /* halves: Wt + epilogue staging stride */

__global__ __launch_bounds__(128)
void k_gemm(const float* __restrict__ H, const float* __restrict__ W) {
    __shared__ __half sWt[64 * WSTRIDE];          // 9.2KB
    __shared__ float sF[4][2][16 * FSTRIDE];      // 4 warps x 2 bufs x 4.6KB
    __shared__ float sSum[F], sSq[F];

    const int tid  = threadIdx.x;
    const int warp = tid >> 5;
    const int lane = tid & 31;
    const int g    = lane >> 2;    // 0..7
    const int tg   = lane & 3;     // 0..3

    const size_t warpRow0 = ((size_t)blockIdx.x * 4 + warp) * (TPW * 16);

    auto stage = [&](int t, float* buf) {
        const float* src = H + (warpRow0 + (size_t)t * 16) * F;
#pragma unroll
        for (int r = 0; r < 8; r++) {
            int f   = lane + 32 * r;      // float4 chunk 0..127
            int row = f >> 4, c4 = f & 15;
            cp_async16(&buf[row * FSTRIDE + c4 * 4], src + (size_t)f * 4);
        }
        asm volatile("cp.async.commit_group;\n" ::);
    };

    // Kick off tile 0 before anything else
    stage(0, sF[warp][0]);

    if (tid < F) { sSum[tid] = 0.f; sSq[tid] = 0.f; }

    // Build Wt (fp16, transposed) in smem
    for (int idx = tid; idx < 64 * 64; idx += 128) {
        int k = idx >> 6, n = idx & 63;
        sWt[n * WSTRIDE + k] = __float2half(W[idx]);
    }
    __syncthreads();

    // Stat accumulators: cols (nt*8 + 2tg) and (+1)
    float s[8][2], q[8][2];
#pragma unroll
    for (int nt = 0; nt < 8; nt++) { s[nt][0] = s[nt][1] = q[nt][0] = q[nt][1] = 0.f; }

#pragma unroll 1
    for (int t = 0; t < TPW; t++) {
        float* buf = sF[warp][t & 1];
        if (t + 1 < TPW) {
            stage(t + 1, sF[warp][(t + 1) & 1]);
            asm volatile("cp.async.wait_group 1;\n" ::);
        } else {
            asm volatile("cp.async.wait_group 0;\n" ::);
        }
        __syncwarp();   // staged data visible warp-wide

        float acc[8][4];
#pragma unroll
        for (int nt = 0; nt < 8; nt++)
#pragma unroll
            for (int i = 0; i < 4; i++) acc[nt][i] = 0.f;

#pragma unroll
        for (int ks = 0; ks < 4; ks++) {
            const int kc = ks * 16 + 2 * tg;
            float2 f0 = *(const float2*)&buf[(g    ) * FSTRIDE + kc    ];
            float2 f1 = *(const float2*)&buf[(g + 8) * FSTRIDE + kc    ];
            float2 f2 = *(const float2*)&buf[(g    ) * FSTRIDE + kc + 8];
            float2 f3 = *(const float2*)&buf[(g + 8) * FSTRIDE + kc + 8];
            uint32_t a0 = h2_bits(__floats2half2_rn(f0.x, f0.y));
            uint32_t a1 = h2_bits(__floats2half2_rn(f1.x, f1.y));
            uint32_t a2 = h2_bits(__floats2half2_rn(f2.x, f2.y));
            uint32_t a3 = h2_bits(__floats2half2_rn(f3.x, f3.y));
#pragma unroll
            for (int nt = 0; nt < 8; nt++) {
                uint32_t b0 = *(const uint32_t*)&sWt[(nt * 8 + g) * WSTRIDE + kc    ];
                uint32_t b1 = *(const uint32_t*)&sWt[(nt * 8 + g) * WSTRIDE + kc + 8];
                asm volatile(
                    "mma.sync.aligned.m16n8k16.row.col.f32.f16.f16.f32 "
                    "{%0,%1,%2,%3}, {%4,%5,%6,%7}, {%8,%9}, {%0,%1,%2,%3};"
                    : "+f"(acc[nt][0]), "+f"(acc[nt][1]),
                      "+f"(acc[nt][2]), "+f"(acc[nt][3])
                    : "r"(a0), "r"(a1), "r"(a2), "r"(a3),
                      "r"(b0), "r"(b1));
            }
        }
        __syncwarp();   // fragment reads done; buffer can be recycled

        // Epilogue: stats + fp16 fragments -> recycled staging buffer
        __half* eb = (__half*)buf;
#pragma unroll
        for (int nt = 0; nt < 8; nt++) {
            int colb = nt * 8 + 2 * tg;
            float c0 = acc[nt][0], c1 = acc[nt][1];
            float c2 = acc[nt][2], c3 = acc[nt][3];
            *(__half2*)&eb[(g    ) * WSTRIDE + colb] = __floats2half2_rn(c0, c1);
            *(__half2*)&eb[(g + 8) * WSTRIDE + colb] = __floats2half2_rn(c2, c3);
            s[nt][0] += c0 + c2;           s[nt][1] += c1 + c3;
            q[nt][0] += c0 * c0 + c2 * c2; q[nt][1] += c1 * c1 + c3 * c3;
        }
        __syncwarp();

        // Dense store: 4 x (LDS.128 + STG.128) covering 16 rows x 128B
        __half* outp = g_Htp + (warpRow0 + (size_t)t * 16) * F;
#pragma unroll
        for (int r = 0; r < 4; r++) {
            int u   = lane + 32 * r;        // 16B unit index, 128 total
            int row = u >> 3, cu = u & 7;
            uint4 x = *(const uint4*)&eb[row * WSTRIDE + cu * 8];
            *(uint4*)&outp[(size_t)row * F + cu * 8] = x;
        }
        __syncwarp();   // epilogue reads done before cp.async refills this buffer
    }

    // Reduce stats: butterfly over g, smem atomics, 64 global atomics
#pragma unroll
    for (int off = 4; off < 32; off <<= 1) {
#pragma unroll
        for (int nt = 0; nt < 8; nt++) {
            s[nt][0] += __shfl_xor_sync(0xffffffffu, s[nt][0], off);
            s[nt][1] += __shfl_xor_sync(0xffffffffu, s[nt][1], off);
            q[nt][0] += __shfl_xor_sync(0xffffffffu, q[nt][0], off);
            q[nt][1] += __shfl_xor_sync(0xffffffffu, q[nt][1], off);
        }
    }
    if (lane < 4) {
#pragma unroll
        for (int nt = 0; nt < 8; nt++) {
            int c = nt * 8 + 2 * lane;
            atomicAdd(&sSum[c],     s[nt][0]);
            atomicAdd(&sSum[c + 1], s[nt][1]);
            atomicAdd(&sSq[c],      q[nt][0]);
            atomicAdd(&sSq[c + 1],  q[nt][1]);
        }
    }
    __syncthreads();
    if (tid < F) {
        atomicAdd(&g_sum[tid],   sSum[tid]);
        atomicAdd(&g_sumsq[tid], sSq[tid]);
    }
}

// ---------------- K2: finalize BN scale/bias ---------------------------------
__global__ void k_stats(const float* __restrict__ gamma, const float* __restrict__ beta) {
    int o = threadIdx.x;
    if (o < F) {
        float inv_m = 1.f / (float)M_TOTAL;
        float mean = g_sum[o] * inv_m;
        float var  = g_sumsq[o] * inv_m - mean * mean;
        float is   = rsqrtf(var + 1e-5f);
        float sc   = gamma[o] * is;
        g_scale[o] = sc;
        g_bias[o]  = beta[o] - mean * sc;
    }
}

// ---------------- K3: BN + ReLU + normalized 3x3 stencil (fp16 in) -----------
// CTA: 288 threads = 18 cols (16 out + 2 halo) x 16 half4 chunks.
// 2 output rows per __syncthreads (4 smem buffers), loads prefetched 2 ahead.
__global__ __launch_bounds__(288, 4)
void k_stencil(float* __restrict__ out) {
    __shared__ float4 cs[4][18][16];

    const int tid   = threadIdx.x;
    const int chunk = tid & 15;      // 0..15 (4 channels each)
    const int colL  = tid >> 4;      // 0..17
    const int b     = blockIdx.z;
    const int j0    = blockIdx.x * 16;
    const int i0    = blockIdx.y * 32;
    const int j     = j0 - 1 + colL;
    const bool jin  = (j >= 0 && j < CDIM);
    const bool isOut = (colL >= 1 && colL <= 16);

    const float4 sc = *(const float4*)&g_scale[chunk * 4];
    const float4 bs = *(const float4*)&g_bias[chunk * 4];
    const __half* base = g_Htp + (size_t)b * NPIX * F;

    auto rawload = [&](int i) -> uint2 {
        if (!jin || i < 0 || i >= RDIM) return make_uint2(0u, 0u);
        return *(const uint2*)&base[((size_t)i * CDIM + j) * F + chunk * 4];
    };
    auto bnrow = [&](uint2 rw, int i) -> float4 {
        if (!jin || i < 0 || i >= RDIM) return make_float4(0.f, 0.f, 0.f, 0.f);
        float2 f0 = __half22float2(*(__half2*)&rw.x);
        float2 f1 = __half22float2(*(__half2*)&rw.y);
        float d = dval(i, j);
        float4 r;
        r.x = fmaxf(fmaf(f0.x, sc.x, bs.x), 0.f) * d;
        r.y = fmaxf(fmaf(f0.y, sc.y, bs.y), 0.f) * d;
        r.z = fmaxf(fmaf(f1.x, sc.z, bs.z), 0.f) * d;
        r.w = fmaxf(fmaf(f1.y, sc.w, bs.w), 0.f) * d;
        return r;
    };

    float4 p = bnrow(rawload(i0 - 1), i0 - 1);
    float4 c = bnrow(rawload(i0), i0);
    uint2 rn  = rawload(i0 + 1);
    uint2 rn2 = rawload(i0 + 2);
    int bb = 0;

    for (int r = 0; r < 16; r++) {
        const int i = i0 + 2 * r;
        uint2 rn3 = rawload(i + 3);
        uint2 rn4 = rawload(i + 4);
        float4 n  = bnrow(rn,  i + 1);
        float4 n2 = bnrow(rn2, i + 2);
        float4 v0, v1;
        v0.x = p.x + c.x + n.x;   v1.x = c.x + n.x + n2.x;
        v0.y = p.y + c.y + n.y;   v1.y = c.y + n.y + n2.y;
        v0.z = p.z + c.z + n.z;   v1.z = c.z + n.z + n2.z;
        v0.w = p.w + c.w + n.w;   v1.w = c.w + n.w + n2.w;
        cs[bb][colL][chunk]     = v0;
        cs[bb + 1][colL][chunk] = v1;
        __syncthreads();
        if (isOut) {
            float4 l0 = cs[bb][colL - 1][chunk];
            float4 r0 = cs[bb][colL + 1][chunk];
            float dc0 = dval(i, j);
            float4 o0;
            o0.x = (l0.x + v0.x + r0.x) * dc0;
            o0.y = (l0.y + v0.y + r0.y) * dc0;
            o0.z = (l0.z + v0.z + r0.z) * dc0;
            o0.w = (l0.w + v0.w + r0.w) * dc0;
            *(float4*)&out[((size_t)b * NPIX + (size_t)i * CDIM + j) * F + chunk * 4] = o0;

            float4 l1 = cs[bb + 1][colL - 1][chunk];
            float4 r1 = cs[bb + 1][colL + 1][chunk];
            float dc1 = dval(i + 1, j);
            float4 o1;
            o1.x = (l1.x + v1.x + r1.x) * dc1;
            o1.y = (l1.y + v1.y + r1.y) * dc1;
            o1.z = (l1.z + v1.z + r1.z) * dc1;
            o1.w = (l1.w + v1.w + r1.w) * dc1;
            *(float4*)&out[((size_t)b * NPIX + (size_t)(i + 1) * CDIM + j) * F + chunk * 4] = o1;
        }
        p = n; c = n2; rn = rn3; rn2 = rn4; bb ^= 2;
    }
}

// ---------------- launch ------------------------------------------------------
extern "C" void kernel_launch(void* const* d_in, const int* in_sizes, int n_in,
                              void* d_out, int out_size) {
    (void)in_sizes; (void)n_in; (void)out_size;
    const float* H     = (const float*)d_in[0];
    const float* W     = (const float*)d_in[1];
    const float* gamma = (const float*)d_in[2];
    const float* beta  = (const float*)d_in[3];
    float* out = (float*)d_out;

    k_zero<<<1, 64>>>();
    const int rows_per_cta = 4 * TPW * 16;   // 1024
    k_gemm<<<M_TOTAL / rows_per_cta, 128>>>(H, W);
    k_stats<<<1, 64>>>(gamma, beta);
    dim3 g3(CDIM / 16, RDIM / 32, BATCH);
    k_stencil<<<g3, 288>>>(out);
}